// round 2
// baseline (speedup 1.0000x reference)
#include <cuda_runtime.h>
#include <cstdint>
#include <math.h>

#define NIR 10
#define EPS2 1e-12f
#define INV_SQRT10 0.31622776601683794f

#define TABN 512
#define RMAX 8.0f
#define DELTA (RMAX / (float)TABN)       // 1/64
#define INV_DELTA ((float)TABN / RMAX)   // 64
#define ROWP 11                           // padded row: 11 float2 (stride coprime with 16 bank-pairs)

// coefficient table: h_v(r) ~= a + b*r on interval k;  [k][v] = (a, b)
__device__ __align__(16) float2 g_tab[TABN][ROWP];

static __device__ __forceinline__ float ex2f(float x){ float r; asm("ex2.approx.f32 %0, %1;" : "=f"(r) : "f"(x)); return r; }
static __device__ __forceinline__ float rcpf(float x){ float r; asm("rcp.approx.f32 %0, %1;" : "=f"(r) : "f"(x)); return r; }
static __device__ __forceinline__ float sqrtaf(float x){ float r; asm("sqrt.approx.f32 %0, %1;" : "=f"(r) : "f"(x)); return r; }

static __device__ __forceinline__ uint64_t pack2(float lo, float hi){
    uint64_t r; asm("mov.b64 %0, {%1, %2};" : "=l"(r) : "f"(lo), "f"(hi)); return r;
}
static __device__ __forceinline__ float2 unpack2(uint64_t v){
    float2 f; asm("mov.b64 {%0, %1}, %2;" : "=f"(f.x), "=f"(f.y) : "l"(v)); return f;
}
static __device__ __forceinline__ uint64_t fma2(uint64_t a, uint64_t b, uint64_t c){
    uint64_t d; asm("fma.rn.f32x2 %0, %1, %2, %3;" : "=l"(d) : "l"(a), "l"(b), "l"(c)); return d;
}

// ---------------- table build (exact chain, float32 like the reference) ----------------
static __device__ void eval_h(float r,
                              const float* __restrict__ lw1, const float* __restrict__ nb1,
                              const float* __restrict__ lw2, const float* __restrict__ nb2,
                              const float* __restrict__ wf, float* h)
{
    float n2 = r * r;
    float g[NIR];
    #pragma unroll
    for (int u = 0; u < NIR; u++){
        float a   = lw1[u];
        float nrm = sqrtf(fmaf(a * a, n2, EPS2));
        g[u] = tanhf(nrm + nb1[u]) / nrm;
    }
    #pragma unroll
    for (int v = 0; v < NIR; v++){
        float c = 0.0f;
        #pragma unroll
        for (int u = 0; u < NIR; u++)
            c = fmaf(g[u] * lw1[u], lw2[u * NIR + v], c);
        c *= INV_SQRT10;
        float nrm2  = sqrtf(fmaf(c * c, n2, EPS2));
        float scal2 = tanhf(nrm2 + nb2[v]) / nrm2;
        h[v] = c * scal2 * wf[v] * INV_SQRT10;
    }
}

__global__ void build_table(const float* __restrict__ lw1, const float* __restrict__ nb1,
                            const float* __restrict__ lw2, const float* __restrict__ nb2,
                            const float* __restrict__ wf)
{
    int k = blockIdx.x * blockDim.x + threadIdx.x;
    if (k >= TABN) return;
    float r0 = (float)k * DELTA;
    float r1 = r0 + DELTA;
    float h0[NIR], h1[NIR];
    eval_h(r0, lw1, nb1, lw2, nb2, wf, h0);
    eval_h(r1, lw1, nb1, lw2, nb2, wf, h1);
    #pragma unroll
    for (int v = 0; v < NIR; v++){
        float bb = (h1[v] - h0[v]) * INV_DELTA;
        float aa = fmaf(-bb, r0, h0[v]);
        g_tab[k][v] = make_float2(aa, bb);
    }
    g_tab[k][10] = make_float2(0.0f, 0.0f);  // padding
}

// ---------------- main kernel ----------------
#define NBB 8   // batches per block

__global__ __launch_bounds__(256) void trq_2b_kernel(
    const float* __restrict__ v1b,   // (B,3)
    const float* __restrict__ invar, // (B,P,2)
    const float* __restrict__ vec2,  // (B,P,6)
    const float* __restrict__ W1,    // (2,10)
    const float* __restrict__ b1,    // (10)
    const float* __restrict__ W2,    // (10,10)
    const float* __restrict__ b2,    // (10)
    float* __restrict__ out,         // (B,3)
    int B)
{
    __shared__ __align__(16) float2 sTab[TABN][ROWP];   // 45056 B
    __shared__ float sW1[2][NIR];
    __shared__ float sB1[NIR], sB2[NIR];
    __shared__ __align__(8) float sW2[NIR][NIR];
    __shared__ float red[3][8];

    const int tid = threadIdx.x;

    if (tid < 100) sW2[tid / 10][tid % 10] = W2[tid];
    if (tid < 20)  sW1[tid / 10][tid % 10] = W1[tid];
    if (tid < 10){ sB1[tid] = b1[tid]; sB2[tid] = b2[tid]; }

    // stage coefficient table into shared (linear float4 copy, 45056 B = 2816 float4)
    {
        const float4* src = reinterpret_cast<const float4*>(&g_tab[0][0]);
        float4* dst = reinterpret_cast<float4*>(&sTab[0][0]);
        #pragma unroll
        for (int i = tid; i < TABN * ROWP * 2 / 4; i += 256)
            dst[i] = src[i];
    }
    __syncthreads();

    #pragma unroll 1
    for (int it = 0; it < NBB; it++){
        const int b = blockIdx.x * NBB + it;
        const size_t e = (size_t)b * 256 + tid;

        const float2 iv = reinterpret_cast<const float2*>(invar)[e];
        const float* vp = vec2 + e * 6;
        const float vx = vp[3], vy = vp[4], vz = vp[5];

        // y1 = relu(invar @ W1 + b1)
        uint64_t y1d[NIR];
        #pragma unroll
        for (int u = 0; u < NIR; u++){
            float y = fmaxf(fmaf(iv.x, sW1[0][u], fmaf(iv.y, sW1[1][u], sB1[u])), 0.0f);
            y1d[u] = pack2(y, y);
        }

        // y2 = relu(y1 @ W2 + b2), f32x2-paired over v
        float y2[NIR];
        #pragma unroll
        for (int j = 0; j < NIR / 2; j++){
            uint64_t acc = pack2(sB2[2 * j], sB2[2 * j + 1]);
            #pragma unroll
            for (int u = 0; u < NIR; u++){
                const uint64_t* wrow = reinterpret_cast<const uint64_t*>(&sW2[u][0]);
                acc = fma2(y1d[u], wrow[j], acc);
            }
            float2 rr = unpack2(acc);
            y2[2 * j]     = fmaxf(rr.x, 0.0f);
            y2[2 * j + 1] = fmaxf(rr.y, 0.0f);
        }

        // r = |v|, table lookup: S = sum_v y2_v * (a_v[k] + b_v[k] * r)
        const float n2 = fmaf(vx, vx, fmaf(vy, vy, vz * vz));
        const float r  = sqrtaf(n2);
        int k = (int)(r * INV_DELTA);
        k = (k > TABN - 1) ? (TABN - 1) : k;

        const float2* row = sTab[k];
        float Sa = 0.0f, Sb = 0.0f;
        #pragma unroll
        for (int v = 0; v < NIR; v++){
            float2 ab = row[v];
            Sa = fmaf(y2[v], ab.x, Sa);
            Sb = fmaf(y2[v], ab.y, Sb);
        }
        const float S = fmaf(r, Sb, Sa);

        float tx = vx * S, ty = vy * S, tz = vz * S;

        // block reduction
        #pragma unroll
        for (int off = 16; off > 0; off >>= 1){
            tx += __shfl_down_sync(0xFFFFFFFFu, tx, off);
            ty += __shfl_down_sync(0xFFFFFFFFu, ty, off);
            tz += __shfl_down_sync(0xFFFFFFFFu, tz, off);
        }
        const int wid = tid >> 5, lane = tid & 31;
        if (lane == 0){ red[0][wid] = tx; red[1][wid] = ty; red[2][wid] = tz; }
        __syncthreads();

        if (tid == 0){
            float sx = 0.0f, sy = 0.0f, sz = 0.0f;
            #pragma unroll
            for (int w = 0; w < 8; w++){ sx += red[0][w]; sy += red[1][w]; sz += red[2][w]; }
            const float a0 = v1b[b * 3 + 0], a1 = v1b[b * 3 + 1], a2 = v1b[b * 3 + 2];
            out[b * 3 + 0] = a1 * sz - a2 * sy;
            out[b * 3 + 1] = a2 * sx - a0 * sz;
            out[b * 3 + 2] = a0 * sy - a1 * sx;
        }
        __syncthreads();
    }
}

extern "C" void kernel_launch(void* const* d_in, const int* in_sizes, int n_in,
                              void* d_out, int out_size)
{
    const float* v1b   = (const float*)d_in[0];
    const float* invar = (const float*)d_in[1];
    const float* vec2  = (const float*)d_in[2];
    const float* W1    = (const float*)d_in[3];
    const float* b1    = (const float*)d_in[4];
    const float* W2    = (const float*)d_in[5];
    const float* b2    = (const float*)d_in[6];
    const float* lw1   = (const float*)d_in[7];
    const float* nb1   = (const float*)d_in[8];
    const float* lw2   = (const float*)d_in[9];
    const float* nb2   = (const float*)d_in[10];
    const float* wf    = (const float*)d_in[11];

    const int B = out_size / 3;   // 4096

    build_table<<<(TABN + 127) / 128, 128>>>(lw1, nb1, lw2, nb2, wf);
    trq_2b_kernel<<<B / NBB, 256>>>(v1b, invar, vec2, W1, b1, W2, b2,
                                    (float*)d_out, B);
}

// round 3
// speedup vs baseline: 1.5907x; 1.5907x over previous
#include <cuda_runtime.h>
#include <cstdint>
#include <math.h>

#define NIR 10
#define EPS2 1e-12f
#define INV_SQRT10 0.31622776601683794f

#define TABN 256
#define RMAX 8.0f
#define DELTA (RMAX / (float)TABN)
#define INV_DELTA ((float)TABN / RMAX)

// coefficient table: h_v(r) ~= a_v + b_v*r on interval k.
// row layout: 7 x float4; j in 0..4 holds (a_{2j}, b_{2j}, a_{2j+1}, b_{2j+1}); j=5,6 pad.
// row stride = 7 float4 = 112B, gcd(7,8)=1 -> uniform bank spread for random k.
__device__ __align__(16) float4 g_tab[TABN][7];

static __device__ __forceinline__ float ex2f(float x){ float r; asm("ex2.approx.f32 %0, %1;" : "=f"(r) : "f"(x)); return r; }
static __device__ __forceinline__ float rcpf(float x){ float r; asm("rcp.approx.f32 %0, %1;" : "=f"(r) : "f"(x)); return r; }
static __device__ __forceinline__ float rsqf(float x){ float r; asm("rsqrt.approx.f32 %0, %1;" : "=f"(r) : "f"(x)); return r; }
static __device__ __forceinline__ float sqrtaf(float x){ float r; asm("sqrt.approx.f32 %0, %1;" : "=f"(r) : "f"(x)); return r; }

static __device__ __forceinline__ float tanh_fast(float z){
    float e = ex2f(z * 2.8853900817779268f);
    float r = rcpf(e + 1.0f);
    return fmaf(-2.0f, r, 1.0f);
}

static __device__ __forceinline__ uint64_t pack2(float lo, float hi){
    uint64_t r; asm("mov.b64 %0, {%1, %2};" : "=l"(r) : "f"(lo), "f"(hi)); return r;
}
static __device__ __forceinline__ float2 unpack2(uint64_t v){
    float2 f; asm("mov.b64 {%0, %1}, %2;" : "=f"(f.x), "=f"(f.y) : "l"(v)); return f;
}
static __device__ __forceinline__ uint64_t fma2(uint64_t a, uint64_t b, uint64_t c){
    uint64_t d; asm("fma.rn.f32x2 %0, %1, %2, %3;" : "=l"(d) : "l"(a), "l"(b), "l"(c)); return d;
}
static __device__ __forceinline__ uint64_t lo64(float4 w){ return pack2(w.x, w.y); }
static __device__ __forceinline__ uint64_t hi64(float4 w){ return pack2(w.z, w.w); }

// ---------------- table build (fast-math chain, proven 2e-7 accurate in R1) ----------------
static __device__ void eval_h(float r,
                              const float* __restrict__ lw1, const float* __restrict__ nb1,
                              const float* __restrict__ lw2, const float* __restrict__ nb2,
                              const float* __restrict__ wf, float* h)
{
    float n2 = r * r;
    float g[NIR];
    #pragma unroll
    for (int u = 0; u < NIR; u++){
        float a   = lw1[u];
        float arg = fmaf(a * a, n2, EPS2);
        float inv = rsqf(arg);
        float nrm = arg * inv;
        g[u] = tanh_fast(nrm + nb1[u]) * inv;
    }
    #pragma unroll
    for (int v = 0; v < NIR; v++){
        float c = 0.0f;
        #pragma unroll
        for (int u = 0; u < NIR; u++)
            c = fmaf(g[u] * lw1[u], lw2[u * NIR + v], c);
        c *= INV_SQRT10;
        float arg = fmaf(c * c, n2, EPS2);
        float inv = rsqf(arg);
        float nrm = arg * inv;
        float scal2 = tanh_fast(nrm + nb2[v]) * inv;
        h[v] = c * scal2 * wf[v] * INV_SQRT10;
    }
}

__global__ void build_table(const float* __restrict__ lw1, const float* __restrict__ nb1,
                            const float* __restrict__ lw2, const float* __restrict__ nb2,
                            const float* __restrict__ wf)
{
    int k = blockIdx.x * blockDim.x + threadIdx.x;
    if (k >= TABN) return;
    float r0 = (float)k * DELTA;
    float h0[NIR], h1[NIR];
    eval_h(r0,         lw1, nb1, lw2, nb2, wf, h0);
    eval_h(r0 + DELTA, lw1, nb1, lw2, nb2, wf, h1);
    #pragma unroll
    for (int j = 0; j < 5; j++){
        float bb0 = (h1[2*j]   - h0[2*j])   * INV_DELTA;
        float bb1 = (h1[2*j+1] - h0[2*j+1]) * INV_DELTA;
        float aa0 = fmaf(-bb0, r0, h0[2*j]);
        float aa1 = fmaf(-bb1, r0, h0[2*j+1]);
        g_tab[k][j] = make_float4(aa0, bb0, aa1, bb1);
    }
    g_tab[k][5] = make_float4(0.f, 0.f, 0.f, 0.f);
    g_tab[k][6] = make_float4(0.f, 0.f, 0.f, 0.f);
}

// ---------------- main kernel: warp-per-batch ----------------
__global__ __launch_bounds__(256) void trq_2b_kernel(
    const float* __restrict__ v1b,   // (B,3)
    const float* __restrict__ invar, // (B,P,2)
    const float* __restrict__ vec2,  // (B,P,6)
    const float* __restrict__ W1,    // (2,10)
    const float* __restrict__ b1,    // (10)
    const float* __restrict__ W2,    // (10,10)
    const float* __restrict__ b2,    // (10)
    float* __restrict__ out)         // (B,3)
{
    __shared__ __align__(16) float4 sTab[TABN][7];   // 28672 B
    __shared__ __align__(16) float4 sW2T[5][5];      // transposed pair layout
    __shared__ float sW1x[NIR], sW1y[NIR], sB1[NIR], sB2[NIR];

    const int tid = threadIdx.x;

    // stage table: 256*7 = 1792 float4, 7 per thread
    {
        const float4* src = &g_tab[0][0];
        float4* dst = &sTab[0][0];
        #pragma unroll
        for (int i = tid; i < TABN * 7; i += 256)
            dst[i] = src[i];
    }
    if (tid < 100){
        int u = tid / 10, v = tid % 10;
        // sW2T[v/2][u/2] component (u&1)*2 + (v&1) = W2[u][v]
        reinterpret_cast<float*>(sW2T)[(v >> 1) * 20 + (u >> 1) * 4 + ((u & 1) << 1) + (v & 1)] = W2[tid];
    }
    if (tid < 10){
        sW1x[tid] = W1[tid];
        sW1y[tid] = W1[10 + tid];
        sB1[tid]  = b1[tid];
        sB2[tid]  = b2[tid];
    }
    __syncthreads();

    const int w    = tid >> 5;
    const int lane = tid & 31;
    const int b    = blockIdx.x * 8 + w;

    // hoist small weights to registers (loop-invariant)
    float w1x[NIR], w1y[NIR], bb1[NIR];
    uint64_t b2d[5];
    #pragma unroll
    for (int u = 0; u < NIR; u++){ w1x[u] = sW1x[u]; w1y[u] = sW1y[u]; bb1[u] = sB1[u]; }
    #pragma unroll
    for (int j = 0; j < 5; j++) b2d[j] = pack2(sB2[2*j], sB2[2*j+1]);

    const size_t e0 = (size_t)b * 256 + lane;
    const float2* ivp = reinterpret_cast<const float2*>(invar) + e0;
    const float*  vb  = vec2 + e0 * 6;

    float tx = 0.f, ty = 0.f, tz = 0.f;

    #pragma unroll 2
    for (int i = 0; i < 8; i++){
        const float2 iv  = ivp[i * 32];
        const float* vp  = vb + i * 32 * 6;
        const float  vx  = vp[3];
        const float2 vyz = *reinterpret_cast<const float2*>(vp + 4);

        // y1 = relu(invar @ W1 + b1), duplicated into f32x2 lanes
        uint64_t y1d[NIR];
        #pragma unroll
        for (int u = 0; u < NIR; u++){
            float y = fmaxf(fmaf(iv.x, w1x[u], fmaf(iv.y, w1y[u], bb1[u])), 0.0f);
            y1d[u] = pack2(y, y);
        }

        // y2 = relu(y1 @ W2 + b2): 25 LDS.128 + 50 fma2
        uint64_t y2d[NIR];
        #pragma unroll
        for (int j = 0; j < 5; j++){
            uint64_t acc = b2d[j];
            #pragma unroll
            for (int uu = 0; uu < 5; uu++){
                float4 wq = sW2T[j][uu];
                acc = fma2(y1d[2*uu],   lo64(wq), acc);
                acc = fma2(y1d[2*uu+1], hi64(wq), acc);
            }
            float2 rr = unpack2(acc);
            float m0 = fmaxf(rr.x, 0.0f);
            float m1 = fmaxf(rr.y, 0.0f);
            y2d[2*j]   = pack2(m0, m0);
            y2d[2*j+1] = pack2(m1, m1);
        }

        // r = |v|, table row k, dot with (a,b) pairs: 5 LDS.128 + 10 fma2
        const float n2 = fmaf(vx, vx, fmaf(vyz.x, vyz.x, vyz.y * vyz.y));
        const float r  = sqrtaf(n2);
        int k = (int)(r * INV_DELTA);
        k = (k > TABN - 1) ? (TABN - 1) : k;

        const float4* row = sTab[k];
        uint64_t acc = 0ull;
        #pragma unroll
        for (int j = 0; j < 5; j++){
            float4 t = row[j];
            acc = fma2(y2d[2*j],   lo64(t), acc);
            acc = fma2(y2d[2*j+1], hi64(t), acc);
        }
        float2 sab = unpack2(acc);
        const float S = fmaf(r, sab.y, sab.x);

        tx = fmaf(vx,    S, tx);
        ty = fmaf(vyz.x, S, ty);
        tz = fmaf(vyz.y, S, tz);
    }

    // warp reduction (warp owns batch b entirely)
    #pragma unroll
    for (int off = 16; off > 0; off >>= 1){
        tx += __shfl_down_sync(0xFFFFFFFFu, tx, off);
        ty += __shfl_down_sync(0xFFFFFFFFu, ty, off);
        tz += __shfl_down_sync(0xFFFFFFFFu, tz, off);
    }
    if (lane == 0){
        const float a0 = v1b[b*3+0], a1 = v1b[b*3+1], a2 = v1b[b*3+2];
        out[b*3+0] = a1 * tz - a2 * ty;
        out[b*3+1] = a2 * tx - a0 * tz;
        out[b*3+2] = a0 * ty - a1 * tx;
    }
}

extern "C" void kernel_launch(void* const* d_in, const int* in_sizes, int n_in,
                              void* d_out, int out_size)
{
    const float* v1b   = (const float*)d_in[0];
    const float* invar = (const float*)d_in[1];
    const float* vec2  = (const float*)d_in[2];
    const float* W1    = (const float*)d_in[3];
    const float* b1    = (const float*)d_in[4];
    const float* W2    = (const float*)d_in[5];
    const float* b2    = (const float*)d_in[6];
    const float* lw1   = (const float*)d_in[7];
    const float* nb1   = (const float*)d_in[8];
    const float* lw2   = (const float*)d_in[9];
    const float* nb2   = (const float*)d_in[10];
    const float* wf    = (const float*)d_in[11];

    const int B = out_size / 3;   // 4096

    build_table<<<2, 128>>>(lw1, nb1, lw2, nb2, wf);
    trq_2b_kernel<<<B / 8, 256>>>(v1b, invar, vec2, W1, b1, W2, b2, (float*)d_out);
}